// round 8
// baseline (speedup 1.0000x reference)
#include <cuda_runtime.h>

#define NND 2048
#define NF  32
#define NC  3
#define NH  35
#define H1  64
#define H2  32

// ---------------- scratch (device globals, no allocs) ----------------
__device__ __align__(16) float g_invn[NND];
__device__ __align__(16) float g_s[NND * NF];          // x^2 * invnorm
__device__ __align__(16) float g_partA[128 * NF];      // chunk sums of g_s (16-row chunks)
__device__ __align__(16) float g_credp[16 * NND * 3];  // per-i-tile centroid partials
__device__ __align__(16) float g_h1[NND * H1];
__device__ __align__(16) float g_partB[128 * H1];      // chunk sums of h1 (16-row chunks)
__device__ __align__(16) float g_A[NND * H2];          // h2 @ Wm1[0:32] + bm1
__device__ __align__(16) float g_B[NND * H2];          // h2 @ Wm1[32:64]
__device__ __align__(16) float g_wd[H2];
__device__ float g_bd;

// ================ K1: norm/partials (blocks 0..127) + centroid tiles (128..263) ================
__global__ void __launch_bounds__(512) k_pre(const float* __restrict__ x,
                                             const float* __restrict__ cent) {
    int blk = blockIdx.x;
    int t = threadIdx.x;
    if (blk < 128) {
        int f = t & 31, r = t >> 5;
        int node = blk * 16 + r;
        float v = x[node * NF + f];
        float sq = v * v;
        float sum = sq;
#pragma unroll
        for (int m = 16; m > 0; m >>= 1) sum += __shfl_xor_sync(0xffffffffu, sum, m);
        float invn = rsqrtf(sum);
        if (f == 0) g_invn[node] = invn;
        float s = sq * invn;
        g_s[node * NF + f] = s;
        __shared__ float sm[16][33];
        sm[r][f] = s;
        __syncthreads();
        if (r < 8) sm[r][f] += sm[r + 8][f];
        __syncthreads();
        if (r < 4) sm[r][f] += sm[r + 4][f];
        __syncthreads();
        if (r < 2) sm[r][f] += sm[r + 2][f];
        __syncthreads();
        if (r == 0) g_partA[blk * NF + f] = sm[0][f] + sm[1][f];
    } else {
        if (t >= 128) return;
        int rr = blk - 128;
        int bj = 0;
        while (rr >= bj + 1) { rr -= bj + 1; bj++; }
        int bi = rr;  // bi <= bj
        __shared__ float sc[3][128];
        int i0 = bi * 128;
        sc[0][t] = cent[(i0 + t) * 3 + 0];
        sc[1][t] = cent[(i0 + t) * 3 + 1];
        sc[2][t] = cent[(i0 + t) * 3 + 2];
        __syncthreads();
        int j = bj * 128 + t;
        float cj0 = cent[j * 3 + 0], cj1 = cent[j * 3 + 1], cj2 = cent[j * 3 + 2];
        int lim = j - i0;
        if (lim > 128) lim = 128;
        float t0 = 0.f, t1 = 0.f, t2 = 0.f;
        for (int il = 0; il < lim; il++) {
            float a = sc[0][il], b = sc[1][il], c = sc[2][il];
            t0 += a * fabsf(a - cj0);
            t1 += b * fabsf(b - cj1);
            t2 += c * fabsf(c - cj2);
        }
        size_t o = ((size_t)bi * NND + j) * 3;
        g_credp[o + 0] = t0;
        g_credp[o + 1] = t1;
        g_credp[o + 2] = t2;
    }
}

// ================ K2: h1 GEMM with fused scan-A offset + cred sums + partB ================
// grid 128, block 512, 16 nodes/block
__global__ void __launch_bounds__(512) k_h1f(const float* __restrict__ x,
                                             const float* __restrict__ cent,
                                             const float* __restrict__ Ws1,
                                             const float* __restrict__ Wn1,
                                             const float* __restrict__ b1) {
    __shared__ float sWs[NH][H1];
    __shared__ float sWn[NH][H1];
    __shared__ float sg[16][33];     // g_s rows for local scan
    __shared__ float soff[NF];       // scan-A block offset
    __shared__ float scred[16][3];   // cred sums per node
    __shared__ float sH[16][36];
    __shared__ float sN[16][36];
    __shared__ float sRed[16][H1 + 1];

    int t = threadIdx.x;
    int blk = blockIdx.x;
    int nbase = blk * 16;

    for (int idx = t; idx < NH * H1; idx += 512) {
        sWs[idx / H1][idx % H1] = Ws1[idx];
        sWn[idx / H1][idx % H1] = Wn1[idx];
    }
    {
        int f = t & 31, n = t >> 5;
        if (n < 16) sg[n][f] = g_s[(nbase + n) * NF + f];
    }
    if (t < 32) {
        int f = t;
        float o0 = 0.f, o1 = 0.f, o2 = 0.f, o3 = 0.f;
        int c = 0;
        for (; c + 4 <= blk; c += 4) {
            o0 += g_partA[(c + 0) * NF + f];
            o1 += g_partA[(c + 1) * NF + f];
            o2 += g_partA[(c + 2) * NF + f];
            o3 += g_partA[(c + 3) * NF + f];
        }
        for (; c < blk; c++) o0 += g_partA[c * NF + f];
        soff[f] = (o0 + o1) + (o2 + o3);
    }
    if (t >= 64 && t < 64 + 48) {
        int nd = t - 64;
        int n = nd / 3, d = nd % 3;
        int node = nbase + n;
        int nt = (node + 127) >> 7;
        float a0 = 0.f, a1 = 0.f;
        int ti = 0;
        for (; ti + 2 <= nt; ti += 2) {
            a0 += g_credp[((size_t)(ti + 0) * NND + node) * 3 + d];
            a1 += g_credp[((size_t)(ti + 1) * NND + node) * 3 + d];
        }
        if (ti < nt) a0 += g_credp[((size_t)ti * NND + node) * 3 + d];
        scred[n][d] = a0 + a1;
    }
    __syncthreads();

    for (int idx = t; idx < 16 * NH; idx += 512) {
        int n = idx / NH, c = idx % NH;
        int node = nbase + n;
        float invdeg = (node > 0) ? (1.f / (float)node) : 0.f;
        float hv, nv;
        if (c < NF) {
            hv = x[node * NF + c];
            float S = soff[c];
            for (int r = 0; r < n; r++) S += sg[r][c];
            nv = invdeg * hv * g_invn[node] * S;
        } else {
            int d = c - NF;
            hv = cent[node * NC + d];
            nv = invdeg * scred[n][d];
        }
        sH[n][c] = hv;
        sN[n][c] = nv;
    }
    __syncthreads();

    int f = t & 63, g = t >> 6;  // g in 0..7 -> nodes g and g+8
    float acc0 = b1[f], acc1 = acc0;
#pragma unroll
    for (int c = 0; c < NH; c++) {
        float ws = sWs[c][f], wn = sWn[c][f];
        acc0 += sH[g][c] * ws + sN[g][c] * wn;
        acc1 += sH[g + 8][c] * ws + sN[g + 8][c] * wn;
    }
    g_h1[(nbase + g) * H1 + f] = acc0;
    g_h1[(nbase + g + 8) * H1 + f] = acc1;

    sRed[g][f] = acc0 + acc1;
    __syncthreads();
    if (g < 4) sRed[g][f] += sRed[g + 4][f];
    __syncthreads();
    if (g < 2) sRed[g][f] += sRed[g + 2][f];
    __syncthreads();
    if (g == 0) g_partB[blk * H1 + f] = sRed[0][f] + sRed[1][f];
}

// ================ K3: h2 + A/B with fused scan-B prefix ================
// grid 256, block 256, 8 nodes/block
__global__ void __launch_bounds__(256) k_h2AB(const float* __restrict__ b2,
                                              const float* __restrict__ Ws2,
                                              const float* __restrict__ Wn2,
                                              const float* __restrict__ Wm1,
                                              const float* __restrict__ bm1,
                                              const float* __restrict__ Wm2,
                                              const float* __restrict__ bm2) {
    __shared__ float sWs2[H1][H2];
    __shared__ float sWn2[H1][H2];
    __shared__ float sWm1[H1][H2];
    __shared__ float sHx[16][H1 + 1];
    __shared__ float sP1[8][H1 + 1];
    __shared__ float h2s[8][H2 + 1];
    __shared__ float soffB[H1];
    __shared__ float red[4][H1];

    int t = threadIdx.x;
    int blk = blockIdx.x;
    int nbase = blk * 8;
    int chunkbase = nbase & ~15;
    int own0 = nbase - chunkbase;  // 0 or 8

    for (int idx = t; idx < H1 * H2; idx += 256) {
        sWs2[idx / H2][idx % H2] = Ws2[idx];
        sWn2[idx / H2][idx % H2] = Wn2[idx];
        sWm1[idx / H2][idx % H2] = Wm1[idx];
    }
    for (int idx = t; idx < 16 * H1; idx += 256) {
        int r = idx >> 6, c = idx & 63;
        sHx[r][c] = g_h1[(chunkbase + r) * H1 + c];
    }
    {
        int grp = t >> 6, c = t & 63;
        int CB = blk >> 1;
        float acc = 0.f;
        for (int ch = grp; ch < CB; ch += 4) acc += g_partB[ch * H1 + c];
        red[grp][c] = acc;
    }
    __syncthreads();
    if (t < 64) soffB[t] = ((red[0][t] + red[1][t]) + (red[2][t] + red[3][t]));
    __syncthreads();
    for (int e = t; e < 8 * H1; e += 256) {
        int n = e >> 6, c = e & 63;
        int node = nbase + n;
        int L = node - chunkbase;
        float s = soffB[c];
        for (int r = 0; r < L; r++) s += sHx[r][c];
        float invdeg = (node > 0) ? (1.f / (float)node) : 0.f;
        sP1[n][c] = s * invdeg;
    }
    __syncthreads();

    int ty = t >> 5, f = t & 31;
    float acc = b2[f];
#pragma unroll 8
    for (int c = 0; c < H1; c++) {
        acc += sHx[own0 + ty][c] * sWs2[c][f] + sP1[ty][c] * sWn2[c][f];
    }
    h2s[ty][f] = acc;
    __syncthreads();
    float accA = bm1[f], accB = 0.f;
#pragma unroll
    for (int c = 0; c < H2; c++) {
        float v = h2s[ty][c];
        accA += v * sWm1[c][f];
        accB += v * sWm1[H2 + c][f];
    }
    int node = nbase + ty;
    g_A[node * H2 + f] = accA;
    g_B[node * H2 + f] = accB;
    if (blk == 0 && ty == 0) {
        g_wd[f] = Wm2[f * 2 + 0] - Wm2[f * 2 + 1];
        if (f == 0) g_bd = bm2[0] - bm2[1];
    }
}

// ================ K4: edge kernel (128x128 tile, 512 thr, 4x8/thread, scalar) ================
#define TT 128
#define TSTR 132   // stride multiple of 4 floats -> 16B-aligned rows (528B = 33*16)
__global__ void __launch_bounds__(512) k_edge(float* __restrict__ out) {
    int bj = blockIdx.x, bi = blockIdx.y;
    if (bi > bj) return;
    int i0 = bi * TT, j0 = bj * TT;

    __shared__ float sAt[H2][TSTR];  // k-major
    __shared__ float sBt[H2][TSTR];
    __shared__ float swd[H2];
    __shared__ float sbd;

    int t = threadIdx.x;  // 512
    {
        const float4* gA4 = (const float4*)(g_A + (size_t)i0 * H2);
        const float4* gB4 = (const float4*)(g_B + (size_t)j0 * H2);
        for (int v = t; v < TT * 8; v += 512) {
            int r = v >> 3, c = (v & 7) * 4;
            float4 qa = gA4[v];
            sAt[c + 0][r] = qa.x; sAt[c + 1][r] = qa.y;
            sAt[c + 2][r] = qa.z; sAt[c + 3][r] = qa.w;
            float4 qb = gB4[v];
            sBt[c + 0][r] = qb.x; sBt[c + 1][r] = qb.y;
            sBt[c + 2][r] = qb.z; sBt[c + 3][r] = qb.w;
        }
        if (t < H2) swd[t] = g_wd[t];
        if (t == 0) sbd = g_bd;
    }
    __syncthreads();

    int tx = t & 15, ty = t >> 4;   // tx: 16 j-groups of 8 contiguous, ty: 32 i-groups of 4
    float acc[4][8];
#pragma unroll
    for (int a = 0; a < 4; a++)
#pragma unroll
        for (int b = 0; b < 8; b++) acc[a][b] = 0.f;

#pragma unroll 4
    for (int k = 0; k < H2; k++) {
        float w = swd[k];
        float4 a0 = *(const float4*)&sAt[k][ty * 4];          // 4 contiguous i (broadcast per half-warp)
        float4 b0 = *(const float4*)&sBt[k][tx * 8];          // 8 contiguous j
        float4 b1 = *(const float4*)&sBt[k][tx * 8 + 4];
        float av[4] = {a0.x, a0.y, a0.z, a0.w};
        float bv[8] = {b0.x, b0.y, b0.z, b0.w, b1.x, b1.y, b1.z, b1.w};
#pragma unroll
        for (int a = 0; a < 4; a++)
#pragma unroll
            for (int b = 0; b < 8; b++)
                acc[a][b] += fmaxf(av[a] + bv[b], 0.f) * w;
    }

    float bd = sbd;
#pragma unroll
    for (int a = 0; a < 4; a++) {
        int i = i0 + ty * 4 + a;
        int basei = i * (2 * NND - 1 - i) / 2 - i - 1;  // e = basei + j
        int jlo = j0 + tx * 8;
#pragma unroll
        for (int b = 0; b < 8; b++) {
            int j = jlo + b;
            if (j > i) {
                float d  = acc[a][b] + bd;  // z0 - z1
                float ex = __expf(-d);
                float p0 = __fdividef(1.f, 1.f + ex);
                float p1 = 1.f - p0;
                ((float2*)out)[basei + j] = make_float2(p0, p1);
            }
        }
    }
}

// ---------------- launch ----------------
extern "C" void kernel_launch(void* const* d_in, const int* in_sizes, int n_in,
                              void* d_out, int out_size) {
    const float* x    = (const float*)d_in[0];
    const float* cent = (const float*)d_in[1];
    const float* Ws1  = (const float*)d_in[2];
    const float* Wn1  = (const float*)d_in[3];
    const float* b1   = (const float*)d_in[4];
    const float* Ws2  = (const float*)d_in[5];
    const float* Wn2  = (const float*)d_in[6];
    const float* b2   = (const float*)d_in[7];
    const float* Wm1  = (const float*)d_in[8];
    const float* bm1  = (const float*)d_in[9];
    const float* Wm2  = (const float*)d_in[10];
    const float* bm2  = (const float*)d_in[11];
    float* out = (float*)d_out;

    k_pre<<<128 + 136, 512>>>(x, cent);
    k_h1f<<<128, 512>>>(x, cent, Ws1, Wn1, b1);
    k_h2AB<<<256, 256>>>(b2, Ws2, Wn2, Wm1, bm1, Wm2, bm2);
    k_edge<<<dim3(16, 16), 512>>>(out);
}

// round 9
// speedup vs baseline: 1.0805x; 1.0805x over previous
#include <cuda_runtime.h>

#define NND 2048
#define NF  32
#define NC  3
#define NH  35
#define H1  64
#define H2  32

// ---------------- scratch (device globals, no allocs) ----------------
__device__ __align__(16) float g_invn[NND];
__device__ __align__(16) float g_s[NND * NF];          // x^2 * invnorm
__device__ __align__(16) float g_partA[128 * NF];      // chunk sums of g_s (16-row chunks)
__device__ __align__(16) float g_credp[16 * NND * 3];  // per-i-tile centroid partials
__device__ __align__(16) float g_h1[NND * H1];
__device__ __align__(16) float g_partB[128 * H1];      // chunk sums of h1 (16-row chunks)
__device__ __align__(16) float g_A[NND * H2];          // h2 @ Wm1[0:32] + bm1
__device__ __align__(16) float g_B[NND * H2];          // h2 @ Wm1[32:64]
__device__ __align__(16) float g_wd[H2];
__device__ float g_bd;

// ================ K1: norm/partials (blocks 0..127) + centroid tiles (128..263) ================
__global__ void __launch_bounds__(512) k_pre(const float* __restrict__ x,
                                             const float* __restrict__ cent) {
    int blk = blockIdx.x;
    int t = threadIdx.x;
    if (blk < 128) {
        int f = t & 31, r = t >> 5;
        int node = blk * 16 + r;
        float v = x[node * NF + f];
        float sq = v * v;
        float sum = sq;
#pragma unroll
        for (int m = 16; m > 0; m >>= 1) sum += __shfl_xor_sync(0xffffffffu, sum, m);
        float invn = rsqrtf(sum);
        if (f == 0) g_invn[node] = invn;
        float s = sq * invn;
        g_s[node * NF + f] = s;
        __shared__ float sm[16][33];
        sm[r][f] = s;
        __syncthreads();
        if (r < 8) sm[r][f] += sm[r + 8][f];
        __syncthreads();
        if (r < 4) sm[r][f] += sm[r + 4][f];
        __syncthreads();
        if (r < 2) sm[r][f] += sm[r + 2][f];
        __syncthreads();
        if (r == 0) g_partA[blk * NF + f] = sm[0][f] + sm[1][f];
    } else {
        if (t >= 128) return;
        int rr = blk - 128;
        int bj = 0;
        while (rr >= bj + 1) { rr -= bj + 1; bj++; }
        int bi = rr;  // bi <= bj
        __shared__ float sc[3][128];
        int i0 = bi * 128;
        sc[0][t] = cent[(i0 + t) * 3 + 0];
        sc[1][t] = cent[(i0 + t) * 3 + 1];
        sc[2][t] = cent[(i0 + t) * 3 + 2];
        __syncthreads();
        int j = bj * 128 + t;
        float cj0 = cent[j * 3 + 0], cj1 = cent[j * 3 + 1], cj2 = cent[j * 3 + 2];
        int lim = j - i0;
        if (lim > 128) lim = 128;
        float t0 = 0.f, t1 = 0.f, t2 = 0.f;
        for (int il = 0; il < lim; il++) {
            float a = sc[0][il], b = sc[1][il], c = sc[2][il];
            t0 += a * fabsf(a - cj0);
            t1 += b * fabsf(b - cj1);
            t2 += c * fabsf(c - cj2);
        }
        size_t o = ((size_t)bi * NND + j) * 3;
        g_credp[o + 0] = t0;
        g_credp[o + 1] = t1;
        g_credp[o + 2] = t2;
    }
}

// ================ K2: h1 GEMM with fused scan-A offset + cred sums + partB ================
// grid 128, block 512, 16 nodes/block
__global__ void __launch_bounds__(512) k_h1f(const float* __restrict__ x,
                                             const float* __restrict__ cent,
                                             const float* __restrict__ Ws1,
                                             const float* __restrict__ Wn1,
                                             const float* __restrict__ b1) {
    __shared__ float sWs[NH][H1];
    __shared__ float sWn[NH][H1];
    __shared__ float sg[16][33];     // g_s rows for local scan
    __shared__ float soff[NF];       // scan-A block offset
    __shared__ float scred[16][3];   // cred sums per node
    __shared__ float sH[16][36];
    __shared__ float sN[16][36];
    __shared__ float sRed[16][H1 + 1];

    int t = threadIdx.x;
    int blk = blockIdx.x;
    int nbase = blk * 16;

    for (int idx = t; idx < NH * H1; idx += 512) {
        sWs[idx / H1][idx % H1] = Ws1[idx];
        sWn[idx / H1][idx % H1] = Wn1[idx];
    }
    {
        int f = t & 31, n = t >> 5;
        if (n < 16) sg[n][f] = g_s[(nbase + n) * NF + f];
    }
    if (t < 32) {
        int f = t;
        float o0 = 0.f, o1 = 0.f, o2 = 0.f, o3 = 0.f;
        int c = 0;
        for (; c + 4 <= blk; c += 4) {
            o0 += g_partA[(c + 0) * NF + f];
            o1 += g_partA[(c + 1) * NF + f];
            o2 += g_partA[(c + 2) * NF + f];
            o3 += g_partA[(c + 3) * NF + f];
        }
        for (; c < blk; c++) o0 += g_partA[c * NF + f];
        soff[f] = (o0 + o1) + (o2 + o3);
    }
    if (t >= 64 && t < 64 + 48) {
        int nd = t - 64;
        int n = nd / 3, d = nd % 3;
        int node = nbase + n;
        int nt = (node + 127) >> 7;
        float a0 = 0.f, a1 = 0.f;
        int ti = 0;
        for (; ti + 2 <= nt; ti += 2) {
            a0 += g_credp[((size_t)(ti + 0) * NND + node) * 3 + d];
            a1 += g_credp[((size_t)(ti + 1) * NND + node) * 3 + d];
        }
        if (ti < nt) a0 += g_credp[((size_t)ti * NND + node) * 3 + d];
        scred[n][d] = a0 + a1;
    }
    __syncthreads();

    for (int idx = t; idx < 16 * NH; idx += 512) {
        int n = idx / NH, c = idx % NH;
        int node = nbase + n;
        float invdeg = (node > 0) ? (1.f / (float)node) : 0.f;
        float hv, nv;
        if (c < NF) {
            hv = x[node * NF + c];
            float S = soff[c];
            for (int r = 0; r < n; r++) S += sg[r][c];
            nv = invdeg * hv * g_invn[node] * S;
        } else {
            int d = c - NF;
            hv = cent[node * NC + d];
            nv = invdeg * scred[n][d];
        }
        sH[n][c] = hv;
        sN[n][c] = nv;
    }
    __syncthreads();

    int f = t & 63, g = t >> 6;  // g in 0..7 -> nodes g and g+8
    float acc0 = b1[f], acc1 = acc0;
#pragma unroll
    for (int c = 0; c < NH; c++) {
        float ws = sWs[c][f], wn = sWn[c][f];
        acc0 += sH[g][c] * ws + sN[g][c] * wn;
        acc1 += sH[g + 8][c] * ws + sN[g + 8][c] * wn;
    }
    g_h1[(nbase + g) * H1 + f] = acc0;
    g_h1[(nbase + g + 8) * H1 + f] = acc1;

    sRed[g][f] = acc0 + acc1;
    __syncthreads();
    if (g < 4) sRed[g][f] += sRed[g + 4][f];
    __syncthreads();
    if (g < 2) sRed[g][f] += sRed[g + 2][f];
    __syncthreads();
    if (g == 0) g_partB[blk * H1 + f] = sRed[0][f] + sRed[1][f];
}

// ================ K3: h2 + A/B with fused scan-B prefix ================
// grid 256, block 256, 8 nodes/block
__global__ void __launch_bounds__(256) k_h2AB(const float* __restrict__ b2,
                                              const float* __restrict__ Ws2,
                                              const float* __restrict__ Wn2,
                                              const float* __restrict__ Wm1,
                                              const float* __restrict__ bm1,
                                              const float* __restrict__ Wm2,
                                              const float* __restrict__ bm2) {
    __shared__ float sWs2[H1][H2];
    __shared__ float sWn2[H1][H2];
    __shared__ float sWm1[H1][H2];
    __shared__ float sHx[16][H1 + 1];
    __shared__ float sP1[8][H1 + 1];
    __shared__ float h2s[8][H2 + 1];
    __shared__ float soffB[H1];
    __shared__ float red[4][H1];

    int t = threadIdx.x;
    int blk = blockIdx.x;
    int nbase = blk * 8;
    int chunkbase = nbase & ~15;
    int own0 = nbase - chunkbase;  // 0 or 8

    for (int idx = t; idx < H1 * H2; idx += 256) {
        sWs2[idx / H2][idx % H2] = Ws2[idx];
        sWn2[idx / H2][idx % H2] = Wn2[idx];
        sWm1[idx / H2][idx % H2] = Wm1[idx];
    }
    for (int idx = t; idx < 16 * H1; idx += 256) {
        int r = idx >> 6, c = idx & 63;
        sHx[r][c] = g_h1[(chunkbase + r) * H1 + c];
    }
    {
        int grp = t >> 6, c = t & 63;
        int CB = blk >> 1;
        float acc = 0.f;
        for (int ch = grp; ch < CB; ch += 4) acc += g_partB[ch * H1 + c];
        red[grp][c] = acc;
    }
    __syncthreads();
    if (t < 64) soffB[t] = ((red[0][t] + red[1][t]) + (red[2][t] + red[3][t]));
    __syncthreads();
    for (int e = t; e < 8 * H1; e += 256) {
        int n = e >> 6, c = e & 63;
        int node = nbase + n;
        int L = node - chunkbase;
        float s = soffB[c];
        for (int r = 0; r < L; r++) s += sHx[r][c];
        float invdeg = (node > 0) ? (1.f / (float)node) : 0.f;
        sP1[n][c] = s * invdeg;
    }
    __syncthreads();

    int ty = t >> 5, f = t & 31;
    float acc = b2[f];
#pragma unroll 8
    for (int c = 0; c < H1; c++) {
        acc += sHx[own0 + ty][c] * sWs2[c][f] + sP1[ty][c] * sWn2[c][f];
    }
    h2s[ty][f] = acc;
    __syncthreads();
    float accA = bm1[f], accB = 0.f;
#pragma unroll
    for (int c = 0; c < H2; c++) {
        float v = h2s[ty][c];
        accA += v * sWm1[c][f];
        accB += v * sWm1[H2 + c][f];
    }
    int node = nbase + ty;
    g_A[node * H2 + f] = accA;
    g_B[node * H2 + f] = accB;
    if (blk == 0 && ty == 0) {
        g_wd[f] = Wm2[f * 2 + 0] - Wm2[f * 2 + 1];
        if (f == 0) g_bd = bm2[0] - bm2[1];
    }
}

// ================ K4: edge kernel — 128(i)x64(j) tiles, 256 thr, 8x4/thread ================
// Linear triangular grid: 272 active blocks, bj >= 2*bi. 2 blocks/SM resident.
#define TI 128
#define TJ 64
#define ASTR (TI + 4)   // 132: 16B-aligned rows
#define BSTR (TJ + 4)   // 68:  16B-aligned rows
__global__ void __launch_bounds__(256, 2) k_edge(float* __restrict__ out) {
    // decode triangular index: counts per bi are (32 - 2*bi)
    int r = blockIdx.x;
    int bi = 0;
    while (r >= 32 - 2 * bi) { r -= 32 - 2 * bi; bi++; }
    int bj = 2 * bi + r;
    int i0 = bi * TI, j0 = bj * TJ;

    __shared__ float sAt[H2][ASTR];  // k-major
    __shared__ float sBt[H2][BSTR];
    __shared__ float swd[H2];
    __shared__ float sbd;

    int t = threadIdx.x;  // 256
    {
        const float4* gA4 = (const float4*)(g_A + (size_t)i0 * H2);
        for (int v = t; v < TI * 8; v += 256) {
            int rr = v >> 3, c = (v & 7) * 4;
            float4 qa = gA4[v];
            sAt[c + 0][rr] = qa.x; sAt[c + 1][rr] = qa.y;
            sAt[c + 2][rr] = qa.z; sAt[c + 3][rr] = qa.w;
        }
        const float4* gB4 = (const float4*)(g_B + (size_t)j0 * H2);
        for (int v = t; v < TJ * 8; v += 256) {
            int rr = v >> 3, c = (v & 7) * 4;
            float4 qb = gB4[v];
            sBt[c + 0][rr] = qb.x; sBt[c + 1][rr] = qb.y;
            sBt[c + 2][rr] = qb.z; sBt[c + 3][rr] = qb.w;
        }
        if (t < H2) swd[t] = g_wd[t];
        if (t == 0) sbd = g_bd;
    }
    __syncthreads();

    int tx = t & 15, ty = t >> 4;   // ty: 16 i-groups of 8; tx: 16 j-groups of 4
    float acc[8][4];
#pragma unroll
    for (int a = 0; a < 8; a++)
#pragma unroll
        for (int b = 0; b < 4; b++) acc[a][b] = 0.f;

#pragma unroll 4
    for (int k = 0; k < H2; k++) {
        float w = swd[k];
        float4 a0 = *(const float4*)&sAt[k][ty * 8];
        float4 a1 = *(const float4*)&sAt[k][ty * 8 + 4];
        float4 b0 = *(const float4*)&sBt[k][tx * 4];
        float av[8] = {a0.x, a0.y, a0.z, a0.w, a1.x, a1.y, a1.z, a1.w};
        float bv[4] = {b0.x, b0.y, b0.z, b0.w};
#pragma unroll
        for (int a = 0; a < 8; a++)
#pragma unroll
            for (int b = 0; b < 4; b++)
                acc[a][b] += fmaxf(av[a] + bv[b], 0.f) * w;
    }

    float bd = sbd;
#pragma unroll
    for (int a = 0; a < 8; a++) {
        int i = i0 + ty * 8 + a;
        int basei = i * (2 * NND - 1 - i) / 2 - i - 1;  // e = basei + j
        int jlo = j0 + tx * 4;
#pragma unroll
        for (int b = 0; b < 4; b++) {
            int j = jlo + b;
            if (j > i) {
                float d  = acc[a][b] + bd;  // z0 - z1
                float ex = __expf(-d);
                float p0 = __fdividef(1.f, 1.f + ex);
                float p1 = 1.f - p0;
                ((float2*)out)[basei + j] = make_float2(p0, p1);
            }
        }
    }
}

// ---------------- launch ----------------
extern "C" void kernel_launch(void* const* d_in, const int* in_sizes, int n_in,
                              void* d_out, int out_size) {
    const float* x    = (const float*)d_in[0];
    const float* cent = (const float*)d_in[1];
    const float* Ws1  = (const float*)d_in[2];
    const float* Wn1  = (const float*)d_in[3];
    const float* b1   = (const float*)d_in[4];
    const float* Ws2  = (const float*)d_in[5];
    const float* Wn2  = (const float*)d_in[6];
    const float* b2   = (const float*)d_in[7];
    const float* Wm1  = (const float*)d_in[8];
    const float* bm1  = (const float*)d_in[9];
    const float* Wm2  = (const float*)d_in[10];
    const float* bm2  = (const float*)d_in[11];
    float* out = (float*)d_out;

    k_pre<<<128 + 136, 512>>>(x, cent);
    k_h1f<<<128, 512>>>(x, cent, Ws1, Wn1, b1);
    k_h2AB<<<256, 256>>>(b2, Ws2, Wn2, Wm1, bm1, Wm2, bm2);
    k_edge<<<272, 256>>>(out);
}

// round 10
// speedup vs baseline: 1.0991x; 1.0172x over previous
#include <cuda_runtime.h>

#define NND 2048
#define NF  32
#define NC  3
#define NH  35
#define H1  64
#define H2  32

// ---------------- scratch (device globals, no allocs) ----------------
__device__ __align__(16) float g_invn[NND];
__device__ __align__(16) float g_s[NND * NF];          // x^2 * invnorm
__device__ __align__(16) float g_partA[128 * NF];      // chunk sums of g_s (16-row chunks)
__device__ __align__(16) float g_credp[16 * NND * 3];  // per-i-tile centroid partials
__device__ __align__(16) float g_h1[NND * H1];
__device__ __align__(16) float g_partB[128 * H1];      // chunk sums of h1 (16-row chunks)
__device__ __align__(16) float g_A[NND * H2];          // h2 @ Wm1[0:32] + bm1
__device__ __align__(16) float g_B[NND * H2];          // h2 @ Wm1[32:64]
__device__ __align__(16) float g_wd[H2];
__device__ float g_bd;

// ================ K1: norm/partials (blocks 0..127) + centroid tiles (128..263) ================
__global__ void __launch_bounds__(512) k_pre(const float* __restrict__ x,
                                             const float* __restrict__ cent) {
    int blk = blockIdx.x;
    int t = threadIdx.x;
    if (blk < 128) {
        int f = t & 31, r = t >> 5;
        int node = blk * 16 + r;
        float v = x[node * NF + f];
        float sq = v * v;
        float sum = sq;
#pragma unroll
        for (int m = 16; m > 0; m >>= 1) sum += __shfl_xor_sync(0xffffffffu, sum, m);
        float invn = rsqrtf(sum);
        if (f == 0) g_invn[node] = invn;
        float s = sq * invn;
        g_s[node * NF + f] = s;
        __shared__ float sm[16][33];
        sm[r][f] = s;
        __syncthreads();
        if (r < 8) sm[r][f] += sm[r + 8][f];
        __syncthreads();
        if (r < 4) sm[r][f] += sm[r + 4][f];
        __syncthreads();
        if (r < 2) sm[r][f] += sm[r + 2][f];
        __syncthreads();
        if (r == 0) g_partA[blk * NF + f] = sm[0][f] + sm[1][f];
    } else {
        if (t >= 128) return;
        int rr = blk - 128;
        int bj = 0;
        while (rr >= bj + 1) { rr -= bj + 1; bj++; }
        int bi = rr;  // bi <= bj
        __shared__ float sc[3][128];
        int i0 = bi * 128;
        sc[0][t] = cent[(i0 + t) * 3 + 0];
        sc[1][t] = cent[(i0 + t) * 3 + 1];
        sc[2][t] = cent[(i0 + t) * 3 + 2];
        __syncthreads();
        int j = bj * 128 + t;
        float cj0 = cent[j * 3 + 0], cj1 = cent[j * 3 + 1], cj2 = cent[j * 3 + 2];
        int lim = j - i0;
        if (lim > 128) lim = 128;
        float t0 = 0.f, t1 = 0.f, t2 = 0.f;
        for (int il = 0; il < lim; il++) {
            float a = sc[0][il], b = sc[1][il], c = sc[2][il];
            t0 += a * fabsf(a - cj0);
            t1 += b * fabsf(b - cj1);
            t2 += c * fabsf(c - cj2);
        }
        size_t o = ((size_t)bi * NND + j) * 3;
        g_credp[o + 0] = t0;
        g_credp[o + 1] = t1;
        g_credp[o + 2] = t2;
    }
}

// ================ K2: h1 GEMM with fused scan-A offset + cred sums + partB ================
// grid 128, block 512, 16 nodes/block
__global__ void __launch_bounds__(512) k_h1f(const float* __restrict__ x,
                                             const float* __restrict__ cent,
                                             const float* __restrict__ Ws1,
                                             const float* __restrict__ Wn1,
                                             const float* __restrict__ b1) {
    __shared__ float sWs[NH][H1];
    __shared__ float sWn[NH][H1];
    __shared__ float sg[16][33];     // g_s rows for local scan
    __shared__ float soff[NF];       // scan-A block offset
    __shared__ float scred[16][3];   // cred sums per node
    __shared__ float sH[16][36];
    __shared__ float sN[16][36];
    __shared__ float sRed[16][H1 + 1];

    int t = threadIdx.x;
    int blk = blockIdx.x;
    int nbase = blk * 16;

    for (int idx = t; idx < NH * H1; idx += 512) {
        sWs[idx / H1][idx % H1] = Ws1[idx];
        sWn[idx / H1][idx % H1] = Wn1[idx];
    }
    {
        int f = t & 31, n = t >> 5;
        if (n < 16) sg[n][f] = g_s[(nbase + n) * NF + f];
    }
    if (t < 32) {
        int f = t;
        float o0 = 0.f, o1 = 0.f, o2 = 0.f, o3 = 0.f;
        int c = 0;
        for (; c + 4 <= blk; c += 4) {
            o0 += g_partA[(c + 0) * NF + f];
            o1 += g_partA[(c + 1) * NF + f];
            o2 += g_partA[(c + 2) * NF + f];
            o3 += g_partA[(c + 3) * NF + f];
        }
        for (; c < blk; c++) o0 += g_partA[c * NF + f];
        soff[f] = (o0 + o1) + (o2 + o3);
    }
    if (t >= 64 && t < 64 + 48) {
        int nd = t - 64;
        int n = nd / 3, d = nd % 3;
        int node = nbase + n;
        int nt = (node + 127) >> 7;
        float a0 = 0.f, a1 = 0.f;
        int ti = 0;
        for (; ti + 2 <= nt; ti += 2) {
            a0 += g_credp[((size_t)(ti + 0) * NND + node) * 3 + d];
            a1 += g_credp[((size_t)(ti + 1) * NND + node) * 3 + d];
        }
        if (ti < nt) a0 += g_credp[((size_t)ti * NND + node) * 3 + d];
        scred[n][d] = a0 + a1;
    }
    __syncthreads();

    for (int idx = t; idx < 16 * NH; idx += 512) {
        int n = idx / NH, c = idx % NH;
        int node = nbase + n;
        float invdeg = (node > 0) ? (1.f / (float)node) : 0.f;
        float hv, nv;
        if (c < NF) {
            hv = x[node * NF + c];
            float S = soff[c];
            for (int r = 0; r < n; r++) S += sg[r][c];
            nv = invdeg * hv * g_invn[node] * S;
        } else {
            int d = c - NF;
            hv = cent[node * NC + d];
            nv = invdeg * scred[n][d];
        }
        sH[n][c] = hv;
        sN[n][c] = nv;
    }
    __syncthreads();

    int f = t & 63, g = t >> 6;  // g in 0..7 -> nodes g and g+8
    float acc0 = b1[f], acc1 = acc0;
#pragma unroll
    for (int c = 0; c < NH; c++) {
        float ws = sWs[c][f], wn = sWn[c][f];
        acc0 += sH[g][c] * ws + sN[g][c] * wn;
        acc1 += sH[g + 8][c] * ws + sN[g + 8][c] * wn;
    }
    g_h1[(nbase + g) * H1 + f] = acc0;
    g_h1[(nbase + g + 8) * H1 + f] = acc1;

    sRed[g][f] = acc0 + acc1;
    __syncthreads();
    if (g < 4) sRed[g][f] += sRed[g + 4][f];
    __syncthreads();
    if (g < 2) sRed[g][f] += sRed[g + 2][f];
    __syncthreads();
    if (g == 0) g_partB[blk * H1 + f] = sRed[0][f] + sRed[1][f];
}

// ================ K3: h2 + A/B with fused scan-B prefix ================
// grid 256, block 256, 8 nodes/block
__global__ void __launch_bounds__(256) k_h2AB(const float* __restrict__ b2,
                                              const float* __restrict__ Ws2,
                                              const float* __restrict__ Wn2,
                                              const float* __restrict__ Wm1,
                                              const float* __restrict__ bm1,
                                              const float* __restrict__ Wm2,
                                              const float* __restrict__ bm2) {
    __shared__ float sWs2[H1][H2];
    __shared__ float sWn2[H1][H2];
    __shared__ float sWm1[H1][H2];
    __shared__ float sHx[16][H1 + 1];
    __shared__ float sP1[8][H1 + 1];
    __shared__ float h2s[8][H2 + 1];
    __shared__ float soffB[H1];
    __shared__ float red[4][H1];

    int t = threadIdx.x;
    int blk = blockIdx.x;
    int nbase = blk * 8;
    int chunkbase = nbase & ~15;
    int own0 = nbase - chunkbase;  // 0 or 8

    for (int idx = t; idx < H1 * H2; idx += 256) {
        sWs2[idx / H2][idx % H2] = Ws2[idx];
        sWn2[idx / H2][idx % H2] = Wn2[idx];
        sWm1[idx / H2][idx % H2] = Wm1[idx];
    }
    for (int idx = t; idx < 16 * H1; idx += 256) {
        int r = idx >> 6, c = idx & 63;
        sHx[r][c] = g_h1[(chunkbase + r) * H1 + c];
    }
    {
        int grp = t >> 6, c = t & 63;
        int CB = blk >> 1;
        float acc = 0.f;
        for (int ch = grp; ch < CB; ch += 4) acc += g_partB[ch * H1 + c];
        red[grp][c] = acc;
    }
    __syncthreads();
    if (t < 64) soffB[t] = ((red[0][t] + red[1][t]) + (red[2][t] + red[3][t]));
    __syncthreads();
    for (int e = t; e < 8 * H1; e += 256) {
        int n = e >> 6, c = e & 63;
        int node = nbase + n;
        int L = node - chunkbase;
        float s = soffB[c];
        for (int r = 0; r < L; r++) s += sHx[r][c];
        float invdeg = (node > 0) ? (1.f / (float)node) : 0.f;
        sP1[n][c] = s * invdeg;
    }
    __syncthreads();

    int ty = t >> 5, f = t & 31;
    float acc = b2[f];
#pragma unroll 8
    for (int c = 0; c < H1; c++) {
        acc += sHx[own0 + ty][c] * sWs2[c][f] + sP1[ty][c] * sWn2[c][f];
    }
    h2s[ty][f] = acc;
    __syncthreads();
    float accA = bm1[f], accB = 0.f;
#pragma unroll
    for (int c = 0; c < H2; c++) {
        float v = h2s[ty][c];
        accA += v * sWm1[c][f];
        accB += v * sWm1[H2 + c][f];
    }
    int node = nbase + ty;
    g_A[node * H2 + f] = accA;
    g_B[node * H2 + f] = accB;
    if (blk == 0 && ty == 0) {
        g_wd[f] = Wm2[f * 2 + 0] - Wm2[f * 2 + 1];
        if (f == 0) g_bd = bm2[0] - bm2[1];
    }
}

// ================ K4: edge kernel — 64x64 tiles, 256 thr, 4x4/thread, 4 blocks/SM ================
// Triangular grid: 528 blocks, bj >= bi.
#define TI 64
#define TJ 64
#define TSTR 68   // stride multiple of 4 floats -> 16B-aligned rows
__global__ void __launch_bounds__(256, 4) k_edge(float* __restrict__ out) {
    // decode triangular index: counts per bi are (32 - bi)
    int r = blockIdx.x;
    int bi = 0;
    while (r >= 32 - bi) { r -= 32 - bi; bi++; }
    int bj = bi + r;
    int i0 = bi * TI, j0 = bj * TJ;

    __shared__ float sAt[H2][TSTR];  // k-major
    __shared__ float sBt[H2][TSTR];
    __shared__ float swd[H2];
    __shared__ float sbd;

    int t = threadIdx.x;  // 256
    {
        const float4* gA4 = (const float4*)(g_A + (size_t)i0 * H2);
        const float4* gB4 = (const float4*)(g_B + (size_t)j0 * H2);
        for (int v = t; v < TI * 8; v += 256) {
            int rr = v >> 3, c = (v & 7) * 4;
            float4 qa = gA4[v];
            sAt[c + 0][rr] = qa.x; sAt[c + 1][rr] = qa.y;
            sAt[c + 2][rr] = qa.z; sAt[c + 3][rr] = qa.w;
            float4 qb = gB4[v];
            sBt[c + 0][rr] = qb.x; sBt[c + 1][rr] = qb.y;
            sBt[c + 2][rr] = qb.z; sBt[c + 3][rr] = qb.w;
        }
        if (t < H2) swd[t] = g_wd[t];
        if (t == 0) sbd = g_bd;
    }
    __syncthreads();

    int tx = t & 15, ty = t >> 4;   // ty: 16 i-groups of 4; tx: 16 j-groups of 4
    float acc[4][4];
#pragma unroll
    for (int a = 0; a < 4; a++)
#pragma unroll
        for (int b = 0; b < 4; b++) acc[a][b] = 0.f;

#pragma unroll 8
    for (int k = 0; k < H2; k++) {
        float w = swd[k];
        float4 a0 = *(const float4*)&sAt[k][ty * 4];
        float4 b0 = *(const float4*)&sBt[k][tx * 4];
        float av[4] = {a0.x, a0.y, a0.z, a0.w};
        float bv[4] = {b0.x, b0.y, b0.z, b0.w};
#pragma unroll
        for (int a = 0; a < 4; a++)
#pragma unroll
            for (int b = 0; b < 4; b++)
                acc[a][b] += fmaxf(av[a] + bv[b], 0.f) * w;
    }

    float bd = sbd;
#pragma unroll
    for (int a = 0; a < 4; a++) {
        int i = i0 + ty * 4 + a;
        int basei = i * (2 * NND - 1 - i) / 2 - i - 1;  // e = basei + j
        int jlo = j0 + tx * 4;
#pragma unroll
        for (int b = 0; b < 4; b++) {
            int j = jlo + b;
            if (j > i) {
                float d  = acc[a][b] + bd;  // z0 - z1
                float ex = __expf(-d);
                float p0 = __fdividef(1.f, 1.f + ex);
                float p1 = 1.f - p0;
                ((float2*)out)[basei + j] = make_float2(p0, p1);
            }
        }
    }
}

// ---------------- launch ----------------
extern "C" void kernel_launch(void* const* d_in, const int* in_sizes, int n_in,
                              void* d_out, int out_size) {
    const float* x    = (const float*)d_in[0];
    const float* cent = (const float*)d_in[1];
    const float* Ws1  = (const float*)d_in[2];
    const float* Wn1  = (const float*)d_in[3];
    const float* b1   = (const float*)d_in[4];
    const float* Ws2  = (const float*)d_in[5];
    const float* Wn2  = (const float*)d_in[6];
    const float* b2   = (const float*)d_in[7];
    const float* Wm1  = (const float*)d_in[8];
    const float* bm1  = (const float*)d_in[9];
    const float* Wm2  = (const float*)d_in[10];
    const float* bm2  = (const float*)d_in[11];
    float* out = (float*)d_out;

    k_pre<<<128 + 136, 512>>>(x, cent);
    k_h1f<<<128, 512>>>(x, cent, Ws1, Wn1, b1);
    k_h2AB<<<256, 256>>>(b2, Ws2, Wn2, Wm1, bm1, Wm2, bm2);
    k_edge<<<528, 256>>>(out);
}

// round 11
// speedup vs baseline: 1.1991x; 1.0911x over previous
#include <cuda_runtime.h>

#define NND 2048
#define NF  32
#define NC  3
#define NH  35
#define H1  64
#define H2  32

// ---------------- scratch (device globals, no allocs) ----------------
__device__ __align__(16) float g_invn[NND];
__device__ __align__(16) float g_s[NND * NF];          // x^2 * invnorm
__device__ __align__(16) float g_partA[128 * NF];      // chunk sums of g_s (16-row chunks)
__device__ __align__(16) float g_credp[16 * NND * 3];  // per-i-tile centroid partials
__device__ __align__(16) float g_h1[NND * H1];
__device__ __align__(16) float g_partB[128 * H1];      // chunk sums of h1 (16-row chunks)
__device__ __align__(16) float g_A[NND * H2];          // h2 @ Wm1[0:32] + bm1
__device__ __align__(16) float g_B[NND * H2];          // h2 @ Wm1[32:64]
__device__ __align__(16) float g_wd[H2];
__device__ float g_bd;

// ================ K1: norm/partials (blocks 0..127) + centroid tiles (128..263) ================
__global__ void __launch_bounds__(512) k_pre(const float* __restrict__ x,
                                             const float* __restrict__ cent) {
    int blk = blockIdx.x;
    int t = threadIdx.x;
    if (blk < 128) {
        int f = t & 31, r = t >> 5;
        int node = blk * 16 + r;
        float v = x[node * NF + f];
        float sq = v * v;
        float sum = sq;
#pragma unroll
        for (int m = 16; m > 0; m >>= 1) sum += __shfl_xor_sync(0xffffffffu, sum, m);
        float invn = rsqrtf(sum);
        if (f == 0) g_invn[node] = invn;
        float s = sq * invn;
        g_s[node * NF + f] = s;
        __shared__ float sm[16][33];
        sm[r][f] = s;
        __syncthreads();
        if (r < 8) sm[r][f] += sm[r + 8][f];
        __syncthreads();
        if (r < 4) sm[r][f] += sm[r + 4][f];
        __syncthreads();
        if (r < 2) sm[r][f] += sm[r + 2][f];
        __syncthreads();
        if (r == 0) g_partA[blk * NF + f] = sm[0][f] + sm[1][f];
    } else {
        if (t >= 128) return;
        int rr = blk - 128;
        int bj = 0;
        while (rr >= bj + 1) { rr -= bj + 1; bj++; }
        int bi = rr;  // bi <= bj
        __shared__ float sc[3][128];
        int i0 = bi * 128;
        sc[0][t] = cent[(i0 + t) * 3 + 0];
        sc[1][t] = cent[(i0 + t) * 3 + 1];
        sc[2][t] = cent[(i0 + t) * 3 + 2];
        __syncthreads();
        int j = bj * 128 + t;
        float cj0 = cent[j * 3 + 0], cj1 = cent[j * 3 + 1], cj2 = cent[j * 3 + 2];
        int lim = j - i0;
        if (lim > 128) lim = 128;
        float t0 = 0.f, t1 = 0.f, t2 = 0.f;
        for (int il = 0; il < lim; il++) {
            float a = sc[0][il], b = sc[1][il], c = sc[2][il];
            t0 += a * fabsf(a - cj0);
            t1 += b * fabsf(b - cj1);
            t2 += c * fabsf(c - cj2);
        }
        size_t o = ((size_t)bi * NND + j) * 3;
        g_credp[o + 0] = t0;
        g_credp[o + 1] = t1;
        g_credp[o + 2] = t2;
    }
}

// ================ K2: h1 GEMM with fused scan-A offset + cred sums + partB ================
// grid 128, block 512, 16 nodes/block
__global__ void __launch_bounds__(512) k_h1f(const float* __restrict__ x,
                                             const float* __restrict__ cent,
                                             const float* __restrict__ Ws1,
                                             const float* __restrict__ Wn1,
                                             const float* __restrict__ b1) {
    __shared__ float sWs[NH][H1];
    __shared__ float sWn[NH][H1];
    __shared__ float sg[16][33];     // g_s rows for local scan
    __shared__ float sredA[8][NF];   // scan-A partials (8 threads per f)
    __shared__ float soff[NF];       // scan-A block offset
    __shared__ float scred[16][3];   // cred sums per node
    __shared__ float sH[16][36];
    __shared__ float sN[16][36];
    __shared__ float sRed[16][H1 + 1];

    int t = threadIdx.x;
    int blk = blockIdx.x;
    int nbase = blk * 16;

    for (int idx = t; idx < NH * H1; idx += 512) {
        sWs[idx / H1][idx % H1] = Ws1[idx];
        sWn[idx / H1][idx % H1] = Wn1[idx];
    }
    {
        int f = t & 31, n = t >> 5;
        if (n < 16) sg[n][f] = g_s[(nbase + n) * NF + f];
    }
    // scan-A offset partials: threads 128..383, 8 per feature, all loads independent
    if (t >= 128 && t < 384) {
        int f = (t - 128) & 31, q = (t - 128) >> 5;
        float a0 = 0.f, a1 = 0.f;
        for (int c = q; c < blk; c += 16) {
            a0 += g_partA[c * NF + f];
            int c2 = c + 8;
            if (c2 < blk) a1 += g_partA[c2 * NF + f];
        }
        sredA[q][f] = a0 + a1;
    }
    // cred sums: threads 64..111, 4 independent accumulators
    if (t >= 64 && t < 64 + 48) {
        int nd = t - 64;
        int n = nd / 3, d = nd % 3;
        int node = nbase + n;
        int nt = (node + 127) >> 7;  // tiles with ti*128 < node
        float a0 = 0.f, a1 = 0.f, a2 = 0.f, a3 = 0.f;
        int ti = 0;
        for (; ti + 4 <= nt; ti += 4) {
            a0 += g_credp[((size_t)(ti + 0) * NND + node) * 3 + d];
            a1 += g_credp[((size_t)(ti + 1) * NND + node) * 3 + d];
            a2 += g_credp[((size_t)(ti + 2) * NND + node) * 3 + d];
            a3 += g_credp[((size_t)(ti + 3) * NND + node) * 3 + d];
        }
        for (; ti < nt; ti++) a0 += g_credp[((size_t)ti * NND + node) * 3 + d];
        scred[n][d] = (a0 + a1) + (a2 + a3);
    }
    __syncthreads();
    if (t < 32) {
        float s = 0.f;
#pragma unroll
        for (int q = 0; q < 8; q++) s += sredA[q][t];
        soff[t] = s;
    }
    __syncthreads();

    for (int idx = t; idx < 16 * NH; idx += 512) {
        int n = idx / NH, c = idx % NH;
        int node = nbase + n;
        float invdeg = (node > 0) ? (1.f / (float)node) : 0.f;
        float hv, nv;
        if (c < NF) {
            hv = x[node * NF + c];
            float S = soff[c];
            for (int r = 0; r < n; r++) S += sg[r][c];
            nv = invdeg * hv * g_invn[node] * S;
        } else {
            int d = c - NF;
            hv = cent[node * NC + d];
            nv = invdeg * scred[n][d];
        }
        sH[n][c] = hv;
        sN[n][c] = nv;
    }
    __syncthreads();

    int f = t & 63, g = t >> 6;  // g in 0..7 -> nodes g and g+8
    float acc0 = b1[f], acc1 = acc0;
#pragma unroll
    for (int c = 0; c < NH; c++) {
        float ws = sWs[c][f], wn = sWn[c][f];
        acc0 += sH[g][c] * ws + sN[g][c] * wn;
        acc1 += sH[g + 8][c] * ws + sN[g + 8][c] * wn;
    }
    g_h1[(nbase + g) * H1 + f] = acc0;
    g_h1[(nbase + g + 8) * H1 + f] = acc1;

    sRed[g][f] = acc0 + acc1;
    __syncthreads();
    if (g < 4) sRed[g][f] += sRed[g + 4][f];
    __syncthreads();
    if (g < 2) sRed[g][f] += sRed[g + 2][f];
    __syncthreads();
    if (g == 0) g_partB[blk * H1 + f] = sRed[0][f] + sRed[1][f];
}

// ================ K3: h2 + A/B with fused scan-B prefix ================
// grid 256, block 256, 8 nodes/block
__global__ void __launch_bounds__(256) k_h2AB(const float* __restrict__ b2,
                                              const float* __restrict__ Ws2,
                                              const float* __restrict__ Wn2,
                                              const float* __restrict__ Wm1,
                                              const float* __restrict__ bm1,
                                              const float* __restrict__ Wm2,
                                              const float* __restrict__ bm2) {
    __shared__ float sWs2[H1][H2];
    __shared__ float sWn2[H1][H2];
    __shared__ float sWm1[H1][H2];
    __shared__ float sHx[16][H1 + 1];
    __shared__ float sP1[8][H1 + 1];
    __shared__ float h2s[8][H2 + 1];
    __shared__ float soffB[H1];
    __shared__ float red[4][H1];

    int t = threadIdx.x;
    int blk = blockIdx.x;
    int nbase = blk * 8;
    int chunkbase = nbase & ~15;
    int own0 = nbase - chunkbase;  // 0 or 8

    for (int idx = t; idx < H1 * H2; idx += 256) {
        sWs2[idx / H2][idx % H2] = Ws2[idx];
        sWn2[idx / H2][idx % H2] = Wn2[idx];
        sWm1[idx / H2][idx % H2] = Wm1[idx];
    }
    for (int idx = t; idx < 16 * H1; idx += 256) {
        int r = idx >> 6, c = idx & 63;
        sHx[r][c] = g_h1[(chunkbase + r) * H1 + c];
    }
    {   // scan-B chunk offsets: 4 threads/f x 8 accumulators -> 32 independent loads
        int grp = t >> 6, c = t & 63;
        int CB = blk >> 1;  // chunks before this block's 16-chunk
        float a[8];
#pragma unroll
        for (int q = 0; q < 8; q++) a[q] = 0.f;
        for (int base = grp; base < CB; base += 32) {
#pragma unroll
            for (int q = 0; q < 8; q++) {
                int cc = base + 4 * q;
                if (cc < CB) a[q] += g_partB[cc * H1 + c];
            }
        }
        red[grp][c] = ((a[0] + a[1]) + (a[2] + a[3])) + ((a[4] + a[5]) + (a[6] + a[7]));
    }
    __syncthreads();
    if (t < 64) soffB[t] = ((red[0][t] + red[1][t]) + (red[2][t] + red[3][t]));
    __syncthreads();
    for (int e = t; e < 8 * H1; e += 256) {
        int n = e >> 6, c = e & 63;
        int node = nbase + n;
        int L = node - chunkbase;
        float s = soffB[c];
        for (int r = 0; r < L; r++) s += sHx[r][c];
        float invdeg = (node > 0) ? (1.f / (float)node) : 0.f;
        sP1[n][c] = s * invdeg;
    }
    __syncthreads();

    int ty = t >> 5, f = t & 31;
    float acc = b2[f];
#pragma unroll 8
    for (int c = 0; c < H1; c++) {
        acc += sHx[own0 + ty][c] * sWs2[c][f] + sP1[ty][c] * sWn2[c][f];
    }
    h2s[ty][f] = acc;
    __syncthreads();
    float accA = bm1[f], accB = 0.f;
#pragma unroll
    for (int c = 0; c < H2; c++) {
        float v = h2s[ty][c];
        accA += v * sWm1[c][f];
        accB += v * sWm1[H2 + c][f];
    }
    int node = nbase + ty;
    g_A[node * H2 + f] = accA;
    g_B[node * H2 + f] = accB;
    if (blk == 0 && ty == 0) {
        g_wd[f] = Wm2[f * 2 + 0] - Wm2[f * 2 + 1];
        if (f == 0) g_bd = bm2[0] - bm2[1];
    }
}

// ================ K4: edge kernel — 64x64 tiles, 256 thr, 4x4/thread, 4 blocks/SM ================
// Triangular grid: 528 blocks, bj >= bi.
#define TI 64
#define TJ 64
#define TSTR 68   // stride multiple of 4 floats -> 16B-aligned rows
__global__ void __launch_bounds__(256, 4) k_edge(float* __restrict__ out) {
    // decode triangular index: counts per bi are (32 - bi)
    int r = blockIdx.x;
    int bi = 0;
    while (r >= 32 - bi) { r -= 32 - bi; bi++; }
    int bj = bi + r;
    int i0 = bi * TI, j0 = bj * TJ;

    __shared__ float sAt[H2][TSTR];  // k-major
    __shared__ float sBt[H2][TSTR];
    __shared__ float swd[H2];
    __shared__ float sbd;

    int t = threadIdx.x;  // 256
    {
        const float4* gA4 = (const float4*)(g_A + (size_t)i0 * H2);
        const float4* gB4 = (const float4*)(g_B + (size_t)j0 * H2);
        for (int v = t; v < TI * 8; v += 256) {
            int rr = v >> 3, c = (v & 7) * 4;
            float4 qa = gA4[v];
            sAt[c + 0][rr] = qa.x; sAt[c + 1][rr] = qa.y;
            sAt[c + 2][rr] = qa.z; sAt[c + 3][rr] = qa.w;
            float4 qb = gB4[v];
            sBt[c + 0][rr] = qb.x; sBt[c + 1][rr] = qb.y;
            sBt[c + 2][rr] = qb.z; sBt[c + 3][rr] = qb.w;
        }
        if (t < H2) swd[t] = g_wd[t];
        if (t == 0) sbd = g_bd;
    }
    __syncthreads();

    int tx = t & 15, ty = t >> 4;   // ty: 16 i-groups of 4; tx: 16 j-groups of 4
    float acc[4][4];
#pragma unroll
    for (int a = 0; a < 4; a++)
#pragma unroll
        for (int b = 0; b < 4; b++) acc[a][b] = 0.f;

#pragma unroll 8
    for (int k = 0; k < H2; k++) {
        float w = swd[k];
        float4 a0 = *(const float4*)&sAt[k][ty * 4];
        float4 b0 = *(const float4*)&sBt[k][tx * 4];
        float av[4] = {a0.x, a0.y, a0.z, a0.w};
        float bv[4] = {b0.x, b0.y, b0.z, b0.w};
#pragma unroll
        for (int a = 0; a < 4; a++)
#pragma unroll
            for (int b = 0; b < 4; b++)
                acc[a][b] += fmaxf(av[a] + bv[b], 0.f) * w;
    }

    float bd = sbd;
#pragma unroll
    for (int a = 0; a < 4; a++) {
        int i = i0 + ty * 4 + a;
        int basei = i * (2 * NND - 1 - i) / 2 - i - 1;  // e = basei + j
        int jlo = j0 + tx * 4;
#pragma unroll
        for (int b = 0; b < 4; b++) {
            int j = jlo + b;
            if (j > i) {
                float d  = acc[a][b] + bd;  // z0 - z1
                float ex = __expf(-d);
                float p0 = __fdividef(1.f, 1.f + ex);
                float p1 = 1.f - p0;
                ((float2*)out)[basei + j] = make_float2(p0, p1);
            }
        }
    }
}

// ---------------- launch ----------------
extern "C" void kernel_launch(void* const* d_in, const int* in_sizes, int n_in,
                              void* d_out, int out_size) {
    const float* x    = (const float*)d_in[0];
    const float* cent = (const float*)d_in[1];
    const float* Ws1  = (const float*)d_in[2];
    const float* Wn1  = (const float*)d_in[3];
    const float* b1   = (const float*)d_in[4];
    const float* Ws2  = (const float*)d_in[5];
    const float* Wn2  = (const float*)d_in[6];
    const float* b2   = (const float*)d_in[7];
    const float* Wm1  = (const float*)d_in[8];
    const float* bm1  = (const float*)d_in[9];
    const float* Wm2  = (const float*)d_in[10];
    const float* bm2  = (const float*)d_in[11];
    float* out = (float*)d_out;

    k_pre<<<128 + 136, 512>>>(x, cent);
    k_h1f<<<128, 512>>>(x, cent, Ws1, Wn1, b1);
    k_h2AB<<<256, 256>>>(b2, Ws2, Wn2, Wm1, bm1, Wm2, bm2);
    k_edge<<<528, 256>>>(out);
}

// round 12
// speedup vs baseline: 1.2063x; 1.0060x over previous
#include <cuda_runtime.h>

#define NND 2048
#define NF  32
#define NC  3
#define NH  35
#define H1  64
#define H2  32

// ---------------- scratch (device globals, no allocs) ----------------
__device__ __align__(16) float g_invn[NND];
__device__ __align__(16) float g_s[NND * NF];          // x^2 * invnorm
__device__ __align__(16) float g_partA[128 * NF];      // chunk sums of g_s (16-row chunks)
__device__ __align__(16) float g_credp[16 * NND * 3];  // per-i-tile centroid partials
__device__ __align__(16) float g_h1[NND * H1];
__device__ __align__(16) float g_partB[128 * H1];      // chunk sums of h1 (16-row chunks)
__device__ __align__(16) float g_A[NND * H2];          // h2 @ Wm1[0:32] + bm1
__device__ __align__(16) float g_B[NND * H2];          // h2 @ Wm1[32:64]
__device__ __align__(16) float g_wd[H2];
__device__ float g_bd;

// ================ K1: norm/partials (blocks 0..127) + centroid tiles (128..263) ================
__global__ void __launch_bounds__(512) k_pre(const float* __restrict__ x,
                                             const float* __restrict__ cent) {
    int blk = blockIdx.x;
    int t = threadIdx.x;
    if (blk < 128) {
        int f = t & 31, r = t >> 5;
        int node = blk * 16 + r;
        float v = x[node * NF + f];
        float sq = v * v;
        float sum = sq;
#pragma unroll
        for (int m = 16; m > 0; m >>= 1) sum += __shfl_xor_sync(0xffffffffu, sum, m);
        float invn = rsqrtf(sum);
        if (f == 0) g_invn[node] = invn;
        float s = sq * invn;
        g_s[node * NF + f] = s;
        __shared__ float sm[16][33];
        sm[r][f] = s;
        __syncthreads();
        if (r < 8) sm[r][f] += sm[r + 8][f];
        __syncthreads();
        if (r < 4) sm[r][f] += sm[r + 4][f];
        __syncthreads();
        if (r < 2) sm[r][f] += sm[r + 2][f];
        __syncthreads();
        if (r == 0) g_partA[blk * NF + f] = sm[0][f] + sm[1][f];
    } else {
        if (t >= 128) return;
        int rr = blk - 128;
        int bj = 0;
        while (rr >= bj + 1) { rr -= bj + 1; bj++; }
        int bi = rr;  // bi <= bj
        __shared__ float sc[3][128];
        int i0 = bi * 128;
        sc[0][t] = cent[(i0 + t) * 3 + 0];
        sc[1][t] = cent[(i0 + t) * 3 + 1];
        sc[2][t] = cent[(i0 + t) * 3 + 2];
        __syncthreads();
        int j = bj * 128 + t;
        float cj0 = cent[j * 3 + 0], cj1 = cent[j * 3 + 1], cj2 = cent[j * 3 + 2];
        int lim = j - i0;
        if (lim > 128) lim = 128;
        float t0 = 0.f, t1 = 0.f, t2 = 0.f;
#pragma unroll 4
        for (int il = 0; il < lim; il++) {
            float a = sc[0][il], b = sc[1][il], c = sc[2][il];
            t0 += a * fabsf(a - cj0);
            t1 += b * fabsf(b - cj1);
            t2 += c * fabsf(c - cj2);
        }
        size_t o = ((size_t)bi * NND + j) * 3;
        g_credp[o + 0] = t0;
        g_credp[o + 1] = t1;
        g_credp[o + 2] = t2;
    }
}

// ================ K2: h1 GEMM with fused scan-A offset + cred sums + partB ================
// grid 128, block 512, 16 nodes/block
__global__ void __launch_bounds__(512) k_h1f(const float* __restrict__ x,
                                             const float* __restrict__ cent,
                                             const float* __restrict__ Ws1,
                                             const float* __restrict__ Wn1,
                                             const float* __restrict__ b1) {
    __shared__ float sWs[NH][H1];
    __shared__ float sWn[NH][H1];
    __shared__ float sg[16][33];     // g_s rows for local scan
    __shared__ float sredA[8][NF];   // scan-A partials (8 threads per f)
    __shared__ float soff[NF];       // scan-A block offset
    __shared__ float scred[16][3];   // cred sums per node
    __shared__ float sH[16][36];
    __shared__ float sN[16][36];
    __shared__ float sRed[16][H1 + 1];

    int t = threadIdx.x;
    int blk = blockIdx.x;
    int nbase = blk * 16;

    for (int idx = t; idx < NH * H1; idx += 512) {
        sWs[idx / H1][idx % H1] = Ws1[idx];
        sWn[idx / H1][idx % H1] = Wn1[idx];
    }
    {
        int f = t & 31, n = t >> 5;
        if (n < 16) sg[n][f] = g_s[(nbase + n) * NF + f];
    }
    // scan-A offset partials: threads 128..383, 8 per feature, all loads independent
    if (t >= 128 && t < 384) {
        int f = (t - 128) & 31, q = (t - 128) >> 5;
        float a0 = 0.f, a1 = 0.f;
        for (int c = q; c < blk; c += 16) {
            a0 += g_partA[c * NF + f];
            int c2 = c + 8;
            if (c2 < blk) a1 += g_partA[c2 * NF + f];
        }
        sredA[q][f] = a0 + a1;
    }
    // cred sums: threads 64..111, 4 independent accumulators
    if (t >= 64 && t < 64 + 48) {
        int nd = t - 64;
        int n = nd / 3, d = nd % 3;
        int node = nbase + n;
        int nt = (node + 127) >> 7;  // tiles with ti*128 < node
        float a0 = 0.f, a1 = 0.f, a2 = 0.f, a3 = 0.f;
        int ti = 0;
        for (; ti + 4 <= nt; ti += 4) {
            a0 += g_credp[((size_t)(ti + 0) * NND + node) * 3 + d];
            a1 += g_credp[((size_t)(ti + 1) * NND + node) * 3 + d];
            a2 += g_credp[((size_t)(ti + 2) * NND + node) * 3 + d];
            a3 += g_credp[((size_t)(ti + 3) * NND + node) * 3 + d];
        }
        for (; ti < nt; ti++) a0 += g_credp[((size_t)ti * NND + node) * 3 + d];
        scred[n][d] = (a0 + a1) + (a2 + a3);
    }
    __syncthreads();
    if (t < 32) {
        float s = 0.f;
#pragma unroll
        for (int q = 0; q < 8; q++) s += sredA[q][t];
        soff[t] = s;
    }
    __syncthreads();

    for (int idx = t; idx < 16 * NH; idx += 512) {
        int n = idx / NH, c = idx % NH;
        int node = nbase + n;
        float invdeg = (node > 0) ? (1.f / (float)node) : 0.f;
        float hv, nv;
        if (c < NF) {
            hv = x[node * NF + c];
            float S = soff[c];
            for (int r = 0; r < n; r++) S += sg[r][c];
            nv = invdeg * hv * g_invn[node] * S;
        } else {
            int d = c - NF;
            hv = cent[node * NC + d];
            nv = invdeg * scred[n][d];
        }
        sH[n][c] = hv;
        sN[n][c] = nv;
    }
    __syncthreads();

    int f = t & 63, g = t >> 6;  // g in 0..7 -> nodes g and g+8
    float acc0 = b1[f], acc1 = acc0;
#pragma unroll
    for (int c = 0; c < NH; c++) {
        float ws = sWs[c][f], wn = sWn[c][f];
        acc0 += sH[g][c] * ws + sN[g][c] * wn;
        acc1 += sH[g + 8][c] * ws + sN[g + 8][c] * wn;
    }
    g_h1[(nbase + g) * H1 + f] = acc0;
    g_h1[(nbase + g + 8) * H1 + f] = acc1;

    sRed[g][f] = acc0 + acc1;
    __syncthreads();
    if (g < 4) sRed[g][f] += sRed[g + 4][f];
    __syncthreads();
    if (g < 2) sRed[g][f] += sRed[g + 2][f];
    __syncthreads();
    if (g == 0) g_partB[blk * H1 + f] = sRed[0][f] + sRed[1][f];
}

// ================ K3: h2 + A/B with fused scan-B prefix ================
// grid 256, block 256, 8 nodes/block
__global__ void __launch_bounds__(256) k_h2AB(const float* __restrict__ b2,
                                              const float* __restrict__ Ws2,
                                              const float* __restrict__ Wn2,
                                              const float* __restrict__ Wm1,
                                              const float* __restrict__ bm1,
                                              const float* __restrict__ Wm2,
                                              const float* __restrict__ bm2) {
    __shared__ float sWs2[H1][H2];
    __shared__ float sWn2[H1][H2];
    __shared__ float sWm1[H1][H2];
    __shared__ float sHx[16][H1 + 1];
    __shared__ float sP1[8][H1 + 1];
    __shared__ float h2s[8][H2 + 1];
    __shared__ float soffB[H1];
    __shared__ float red[4][H1];

    int t = threadIdx.x;
    int blk = blockIdx.x;
    int nbase = blk * 8;
    int chunkbase = nbase & ~15;
    int own0 = nbase - chunkbase;  // 0 or 8

    for (int idx = t; idx < H1 * H2; idx += 256) {
        sWs2[idx / H2][idx % H2] = Ws2[idx];
        sWn2[idx / H2][idx % H2] = Wn2[idx];
        sWm1[idx / H2][idx % H2] = Wm1[idx];
    }
    for (int idx = t; idx < 16 * H1; idx += 256) {
        int r = idx >> 6, c = idx & 63;
        sHx[r][c] = g_h1[(chunkbase + r) * H1 + c];
    }
    {   // scan-B chunk offsets: 4 threads/f x 8 accumulators -> 32 independent loads
        int grp = t >> 6, c = t & 63;
        int CB = blk >> 1;  // chunks before this block's 16-chunk
        float a[8];
#pragma unroll
        for (int q = 0; q < 8; q++) a[q] = 0.f;
        for (int base = grp; base < CB; base += 32) {
#pragma unroll
            for (int q = 0; q < 8; q++) {
                int cc = base + 4 * q;
                if (cc < CB) a[q] += g_partB[cc * H1 + c];
            }
        }
        red[grp][c] = ((a[0] + a[1]) + (a[2] + a[3])) + ((a[4] + a[5]) + (a[6] + a[7]));
    }
    __syncthreads();
    if (t < 64) soffB[t] = ((red[0][t] + red[1][t]) + (red[2][t] + red[3][t]));
    __syncthreads();
    for (int e = t; e < 8 * H1; e += 256) {
        int n = e >> 6, c = e & 63;
        int node = nbase + n;
        int L = node - chunkbase;
        float s = soffB[c];
        for (int r = 0; r < L; r++) s += sHx[r][c];
        float invdeg = (node > 0) ? (1.f / (float)node) : 0.f;
        sP1[n][c] = s * invdeg;
    }
    __syncthreads();

    int ty = t >> 5, f = t & 31;
    float acc = b2[f];
#pragma unroll 8
    for (int c = 0; c < H1; c++) {
        acc += sHx[own0 + ty][c] * sWs2[c][f] + sP1[ty][c] * sWn2[c][f];
    }
    h2s[ty][f] = acc;
    __syncthreads();
    float accA = bm1[f], accB = 0.f;
#pragma unroll
    for (int c = 0; c < H2; c++) {
        float v = h2s[ty][c];
        accA += v * sWm1[c][f];
        accB += v * sWm1[H2 + c][f];
    }
    int node = nbase + ty;
    g_A[node * H2 + f] = accA;
    g_B[node * H2 + f] = accB;
    if (blk == 0 && ty == 0) {
        g_wd[f] = Wm2[f * 2 + 0] - Wm2[f * 2 + 1];
        if (f == 0) g_bd = bm2[0] - bm2[1];
    }
}

// ================ K4: edge kernel — 64(i)x32(j) tiles, 128 thr, 4x4/thread, 8 blocks/SM ================
// Triangular grid over (bi: 32 i-tiles of 64) x (bj: 64 j-tiles of 32), keep bj >= 2*bi.
// count per bi = 64 - 2*bi -> total 1056 blocks.
#define TI 64
#define TJ 32
#define ASTR 68   // 64+4: 16B-aligned rows
#define BSTR 36   // 32+4: 16B-aligned rows
__global__ void __launch_bounds__(128, 8) k_edge(float* __restrict__ out) {
    int r = blockIdx.x;
    int bi = 0;
    while (r >= 64 - 2 * bi) { r -= 64 - 2 * bi; bi++; }
    int bj = 2 * bi + r;
    int i0 = bi * TI, j0 = bj * TJ;

    __shared__ float sAt[H2][ASTR];  // k-major
    __shared__ float sBt[H2][BSTR];
    __shared__ float swd[H2];
    __shared__ float sbd;

    int t = threadIdx.x;  // 128
    {
        const float4* gA4 = (const float4*)(g_A + (size_t)i0 * H2);
#pragma unroll
        for (int u = 0; u < 4; u++) {
            int v = t + u * 128;
            int rr = v >> 3, c = (v & 7) * 4;
            float4 qa = gA4[v];
            sAt[c + 0][rr] = qa.x; sAt[c + 1][rr] = qa.y;
            sAt[c + 2][rr] = qa.z; sAt[c + 3][rr] = qa.w;
        }
        const float4* gB4 = (const float4*)(g_B + (size_t)j0 * H2);
#pragma unroll
        for (int u = 0; u < 2; u++) {
            int v = t + u * 128;
            int rr = v >> 3, c = (v & 7) * 4;
            float4 qb = gB4[v];
            sBt[c + 0][rr] = qb.x; sBt[c + 1][rr] = qb.y;
            sBt[c + 2][rr] = qb.z; sBt[c + 3][rr] = qb.w;
        }
        if (t < H2) swd[t] = g_wd[t];
        if (t == 0) sbd = g_bd;
    }
    __syncthreads();

    int tx = t & 7, ty = t >> 3;   // ty: 16 i-groups of 4; tx: 8 j-groups of 4
    float acc[4][4];
#pragma unroll
    for (int a = 0; a < 4; a++)
#pragma unroll
        for (int b = 0; b < 4; b++) acc[a][b] = 0.f;

#pragma unroll
    for (int k = 0; k < H2; k++) {
        float w = swd[k];
        float4 a0 = *(const float4*)&sAt[k][ty * 4];
        float4 b0 = *(const float4*)&sBt[k][tx * 4];
        float av[4] = {a0.x, a0.y, a0.z, a0.w};
        float bv[4] = {b0.x, b0.y, b0.z, b0.w};
#pragma unroll
        for (int a = 0; a < 4; a++)
#pragma unroll
            for (int b = 0; b < 4; b++)
                acc[a][b] += fmaxf(av[a] + bv[b], 0.f) * w;
    }

    float bd = sbd;
#pragma unroll
    for (int a = 0; a < 4; a++) {
        int i = i0 + ty * 4 + a;
        int basei = i * (2 * NND - 1 - i) / 2 - i - 1;  // e = basei + j
        int jlo = j0 + tx * 4;
#pragma unroll
        for (int b = 0; b < 4; b++) {
            int j = jlo + b;
            if (j > i) {
                float d  = acc[a][b] + bd;  // z0 - z1
                float ex = __expf(-d);
                float p0 = __fdividef(1.f, 1.f + ex);
                float p1 = 1.f - p0;
                ((float2*)out)[basei + j] = make_float2(p0, p1);
            }
        }
    }
}

// ---------------- launch ----------------
extern "C" void kernel_launch(void* const* d_in, const int* in_sizes, int n_in,
                              void* d_out, int out_size) {
    const float* x    = (const float*)d_in[0];
    const float* cent = (const float*)d_in[1];
    const float* Ws1  = (const float*)d_in[2];
    const float* Wn1  = (const float*)d_in[3];
    const float* b1   = (const float*)d_in[4];
    const float* Ws2  = (const float*)d_in[5];
    const float* Wn2  = (const float*)d_in[6];
    const float* b2   = (const float*)d_in[7];
    const float* Wm1  = (const float*)d_in[8];
    const float* bm1  = (const float*)d_in[9];
    const float* Wm2  = (const float*)d_in[10];
    const float* bm2  = (const float*)d_in[11];
    float* out = (float*)d_out;

    k_pre<<<128 + 136, 512>>>(x, cent);
    k_h1f<<<128, 512>>>(x, cent, Ws1, Wn1, b1);
    k_h2AB<<<256, 256>>>(b2, Ws2, Wn2, Wm1, bm1, Wm2, bm2);
    k_edge<<<1056, 128>>>(out);
}

// round 13
// speedup vs baseline: 1.2126x; 1.0052x over previous
#include <cuda_runtime.h>

#define NND 2048
#define NF  32
#define NC  3
#define NH  35
#define H1  64
#define H2  32
#define GRID_N 272u

// ---------------- scratch (device globals, no allocs) ----------------
__device__ __align__(16) float g_invn[NND];
__device__ __align__(16) float g_s[NND * NF];          // x^2 * invnorm
__device__ __align__(16) float g_partA[128 * NF];      // chunk sums of g_s (16-row chunks)
__device__ __align__(16) float g_credp[16 * NND * 3];  // per-i-tile centroid partials
__device__ __align__(16) float g_h1[NND * H1];
__device__ __align__(16) float g_partB[128 * H1];      // chunk sums of h1 (16-row chunks)
__device__ __align__(16) float g_A[NND * H2];          // h2 @ Wm1[0:32] + bm1
__device__ __align__(16) float g_B[NND * H2];          // h2 @ Wm1[32:64]
__device__ __align__(16) float g_wd[H2];
__device__ float g_bd;

// barrier counters (monotonic across graph replays; no reset needed)
__device__ unsigned g_bar1, g_bar2, g_bar3;

__device__ __forceinline__ void gbarrier(unsigned* ctr) {
    __syncthreads();
    if (threadIdx.x == 0) {
        __threadfence();
        unsigned ticket = atomicAdd(ctr, 1u);
        unsigned target = (ticket / GRID_N + 1u) * GRID_N;
        while (atomicAdd(ctr, 0u) < target) { __nanosleep(64); }
        __threadfence();
    }
    __syncthreads();
}

// ---------------- shared-memory union across phases ----------------
struct SP1a { float sm[16][33]; };
struct SP1b { float sc[3][128]; };
struct SP2 {
    float sWs[NH][H1];
    float sWn[NH][H1];
    float sg[16][33];
    float sredA[8][NF];
    float soff[NF];
    float scred[16][3];
    float sH[16][36];
    float sN[16][36];
    float sRed[16][H1 + 1];
};
struct SP3 {
    float sWs2[H1][H2];
    float sWn2[H1][H2];
    float sWm1[H1][H2];
    float sHx[16][H1 + 1];
    float sP1[16][H1 + 1];
    float h2s[16][H2 + 1];
    float soffB[H1];
    float red[8][H1];
};
struct SP4 {
    float sAt[H2][68];    // k-major A tile (64 i + pad)
    float sBt[H2][132];   // k-major B tile (128 j + pad)
    float swd[H2];
    float sbd;
};
union SU { SP1a p1a; SP1b p1b; SP2 p2; SP3 p3; SP4 p4; };

// ================ single fused kernel: 272 blocks x 512 threads ================
__global__ void __launch_bounds__(512, 2) k_fused(
    const float* __restrict__ x, const float* __restrict__ cent,
    const float* __restrict__ Ws1, const float* __restrict__ Wn1,
    const float* __restrict__ b1,
    const float* __restrict__ Ws2, const float* __restrict__ Wn2,
    const float* __restrict__ b2,
    const float* __restrict__ Wm1, const float* __restrict__ bm1,
    const float* __restrict__ Wm2, const float* __restrict__ bm2,
    float* __restrict__ out)
{
    __shared__ SU su;
    int blk = blockIdx.x;
    int t = threadIdx.x;

    // ================= Phase 1 =================
    if (blk < 128) {
        // normsum: 16 nodes/block
        int f = t & 31, r = t >> 5;
        int node = blk * 16 + r;
        float v = x[node * NF + f];
        float sq = v * v;
        float sum = sq;
#pragma unroll
        for (int m = 16; m > 0; m >>= 1) sum += __shfl_xor_sync(0xffffffffu, sum, m);
        float invn = rsqrtf(sum);
        if (f == 0) g_invn[node] = invn;
        float s = sq * invn;
        g_s[node * NF + f] = s;
        su.p1a.sm[r][f] = s;
        __syncthreads();
        if (r < 8) su.p1a.sm[r][f] += su.p1a.sm[r + 8][f];
        __syncthreads();
        if (r < 4) su.p1a.sm[r][f] += su.p1a.sm[r + 4][f];
        __syncthreads();
        if (r < 2) su.p1a.sm[r][f] += su.p1a.sm[r + 2][f];
        __syncthreads();
        if (r == 0) g_partA[blk * NF + f] = su.p1a.sm[0][f] + su.p1a.sm[1][f];
    } else if (blk < 264) {
        // centroid |diff| tile partials: 136 triangular 128x128 tiles
        int rr = blk - 128;
        int bj = 0;
        while (rr >= bj + 1) { rr -= bj + 1; bj++; }
        int bi = rr;  // bi <= bj
        int i0 = bi * 128;
        if (t < 128) {
            su.p1b.sc[0][t] = cent[(i0 + t) * 3 + 0];
            su.p1b.sc[1][t] = cent[(i0 + t) * 3 + 1];
            su.p1b.sc[2][t] = cent[(i0 + t) * 3 + 2];
        }
        __syncthreads();
        if (t < 128) {
            int j = bj * 128 + t;
            float cj0 = cent[j * 3 + 0], cj1 = cent[j * 3 + 1], cj2 = cent[j * 3 + 2];
            int lim = j - i0;
            if (lim > 128) lim = 128;
            float t0 = 0.f, t1 = 0.f, t2 = 0.f;
#pragma unroll 4
            for (int il = 0; il < lim; il++) {
                float a = su.p1b.sc[0][il], b = su.p1b.sc[1][il], c = su.p1b.sc[2][il];
                t0 += a * fabsf(a - cj0);
                t1 += b * fabsf(b - cj1);
                t2 += c * fabsf(c - cj2);
            }
            size_t o = ((size_t)bi * NND + j) * 3;
            g_credp[o + 0] = t0;
            g_credp[o + 1] = t1;
            g_credp[o + 2] = t2;
        }
    }

    gbarrier(&g_bar1);

    // ================= Phase 2: h1 GEMM (blocks 0..127, 16 nodes each) =================
    if (blk < 128) {
        int nbase = blk * 16;
        for (int idx = t; idx < NH * H1; idx += 512) {
            su.p2.sWs[idx / H1][idx % H1] = Ws1[idx];
            su.p2.sWn[idx / H1][idx % H1] = Wn1[idx];
        }
        {
            int f = t & 31, n = t >> 5;
            if (n < 16) su.p2.sg[n][f] = g_s[(nbase + n) * NF + f];
        }
        if (t >= 128 && t < 384) {  // scan-A offset partials, 8 threads/feature
            int f = (t - 128) & 31, q = (t - 128) >> 5;
            float a0 = 0.f, a1 = 0.f;
            for (int c = q; c < blk; c += 16) {
                a0 += g_partA[c * NF + f];
                int c2 = c + 8;
                if (c2 < blk) a1 += g_partA[c2 * NF + f];
            }
            su.p2.sredA[q][f] = a0 + a1;
        }
        if (t >= 64 && t < 64 + 48) {  // cred sums, 4 accumulators
            int nd = t - 64;
            int n = nd / 3, d = nd % 3;
            int node = nbase + n;
            int nt = (node + 127) >> 7;
            float a0 = 0.f, a1 = 0.f, a2 = 0.f, a3 = 0.f;
            int ti = 0;
            for (; ti + 4 <= nt; ti += 4) {
                a0 += g_credp[((size_t)(ti + 0) * NND + node) * 3 + d];
                a1 += g_credp[((size_t)(ti + 1) * NND + node) * 3 + d];
                a2 += g_credp[((size_t)(ti + 2) * NND + node) * 3 + d];
                a3 += g_credp[((size_t)(ti + 3) * NND + node) * 3 + d];
            }
            for (; ti < nt; ti++) a0 += g_credp[((size_t)ti * NND + node) * 3 + d];
            su.p2.scred[n][d] = (a0 + a1) + (a2 + a3);
        }
        __syncthreads();
        if (t < 32) {
            float s = 0.f;
#pragma unroll
            for (int q = 0; q < 8; q++) s += su.p2.sredA[q][t];
            su.p2.soff[t] = s;
        }
        __syncthreads();

        for (int idx = t; idx < 16 * NH; idx += 512) {
            int n = idx / NH, c = idx % NH;
            int node = nbase + n;
            float invdeg = (node > 0) ? (1.f / (float)node) : 0.f;
            float hv, nv;
            if (c < NF) {
                hv = x[node * NF + c];
                float S = su.p2.soff[c];
                for (int r = 0; r < n; r++) S += su.p2.sg[r][c];
                nv = invdeg * hv * g_invn[node] * S;
            } else {
                int d = c - NF;
                hv = cent[node * NC + d];
                nv = invdeg * su.p2.scred[n][d];
            }
            su.p2.sH[n][c] = hv;
            su.p2.sN[n][c] = nv;
        }
        __syncthreads();

        int f = t & 63, g = t >> 6;  // g in 0..7 -> nodes g and g+8
        float acc0 = b1[f], acc1 = acc0;
#pragma unroll
        for (int c = 0; c < NH; c++) {
            float ws = su.p2.sWs[c][f], wn = su.p2.sWn[c][f];
            acc0 += su.p2.sH[g][c] * ws + su.p2.sN[g][c] * wn;
            acc1 += su.p2.sH[g + 8][c] * ws + su.p2.sN[g + 8][c] * wn;
        }
        g_h1[(nbase + g) * H1 + f] = acc0;
        g_h1[(nbase + g + 8) * H1 + f] = acc1;

        su.p2.sRed[g][f] = acc0 + acc1;
        __syncthreads();
        if (g < 4) su.p2.sRed[g][f] += su.p2.sRed[g + 4][f];
        __syncthreads();
        if (g < 2) su.p2.sRed[g][f] += su.p2.sRed[g + 2][f];
        __syncthreads();
        if (g == 0) g_partB[blk * H1 + f] = su.p2.sRed[0][f] + su.p2.sRed[1][f];
    }

    gbarrier(&g_bar2);

    // ================= Phase 3: h2 + A/B (blocks 0..127, 16 nodes each) =================
    if (blk < 128) {
        int nbase = blk * 16;
        for (int idx = t; idx < H1 * H2; idx += 512) {
            su.p3.sWs2[idx / H2][idx % H2] = Ws2[idx];
            su.p3.sWn2[idx / H2][idx % H2] = Wn2[idx];
            su.p3.sWm1[idx / H2][idx % H2] = Wm1[idx];
        }
        for (int idx = t; idx < 16 * H1; idx += 512) {
            int r = idx >> 6, c = idx & 63;
            su.p3.sHx[r][c] = g_h1[(nbase + r) * H1 + c];
        }
        {   // scan-B chunk offsets: 8 groups x 4 accumulators -> 32 independent loads
            int grp = t >> 6, c = t & 63;
            int CB = blk;  // 16-node chunks before this block
            float a0 = 0.f, a1 = 0.f, a2 = 0.f, a3 = 0.f;
            for (int base = grp; base < CB; base += 32) {
                a0 += g_partB[base * H1 + c];
                if (base + 8 < CB)  a1 += g_partB[(base + 8) * H1 + c];
                if (base + 16 < CB) a2 += g_partB[(base + 16) * H1 + c];
                if (base + 24 < CB) a3 += g_partB[(base + 24) * H1 + c];
            }
            su.p3.red[grp][c] = (a0 + a1) + (a2 + a3);
        }
        __syncthreads();
        if (t < 64) {
            float s = 0.f;
#pragma unroll
            for (int g = 0; g < 8; g++) s += su.p3.red[g][t];
            su.p3.soffB[t] = s;
        }
        __syncthreads();
        for (int e = t; e < 16 * H1; e += 512) {
            int n = e >> 6, c = e & 63;
            int node = nbase + n;
            float s = su.p3.soffB[c];
            for (int r = 0; r < n; r++) s += su.p3.sHx[r][c];
            float invdeg = (node > 0) ? (1.f / (float)node) : 0.f;
            su.p3.sP1[n][c] = s * invdeg;
        }
        __syncthreads();

        int ty = t >> 5, f = t & 31;  // 16 nodes x 32 features
        float acc = b2[f];
#pragma unroll 8
        for (int c = 0; c < H1; c++) {
            acc += su.p3.sHx[ty][c] * su.p3.sWs2[c][f] + su.p3.sP1[ty][c] * su.p3.sWn2[c][f];
        }
        su.p3.h2s[ty][f] = acc;
        __syncthreads();
        float accA = bm1[f], accB = 0.f;
#pragma unroll
        for (int c = 0; c < H2; c++) {
            float v = su.p3.h2s[ty][c];
            accA += v * su.p3.sWm1[c][f];
            accB += v * su.p3.sWm1[H2 + c][f];
        }
        int node = nbase + ty;
        g_A[node * H2 + f] = accA;
        g_B[node * H2 + f] = accB;
        if (blk == 0 && ty == 0) {
            g_wd[f] = Wm2[f * 2 + 0] - Wm2[f * 2 + 1];
            if (f == 0) g_bd = bm2[0] - bm2[1];
        }
    }

    gbarrier(&g_bar3);

    // ================= Phase 4: edge — one 64(i)x128(j) tile per block =================
    {
        // triangular decode: count per bi = 16 - bi/2, total 272
        int rr = blk;
        int bi = 0;
        while (rr >= 16 - (bi >> 1)) { rr -= 16 - (bi >> 1); bi++; }
        int bj = (bi >> 1) + rr;
        int i0 = bi * 64, j0 = bj * 128;

        {
            const float4* gA4 = (const float4*)(g_A + (size_t)i0 * H2);
            {   // 512 float4 of A
                int v = t;
                int r = v >> 3, c = (v & 7) * 4;
                float4 qa = gA4[v];
                su.p4.sAt[c + 0][r] = qa.x; su.p4.sAt[c + 1][r] = qa.y;
                su.p4.sAt[c + 2][r] = qa.z; su.p4.sAt[c + 3][r] = qa.w;
            }
            const float4* gB4 = (const float4*)(g_B + (size_t)j0 * H2);
#pragma unroll
            for (int u = 0; u < 2; u++) {  // 1024 float4 of B
                int v = t + u * 512;
                int r = v >> 3, c = (v & 7) * 4;
                float4 qb = gB4[v];
                su.p4.sBt[c + 0][r] = qb.x; su.p4.sBt[c + 1][r] = qb.y;
                su.p4.sBt[c + 2][r] = qb.z; su.p4.sBt[c + 3][r] = qb.w;
            }
            if (t < H2) su.p4.swd[t] = g_wd[t];
            if (t == 0) su.p4.sbd = g_bd;
        }
        __syncthreads();

        int tx = t & 31, ty = t >> 5;  // ty: 16 i-groups of 4; tx: 32 j-groups of 4
        float acc[4][4];
#pragma unroll
        for (int a = 0; a < 4; a++)
#pragma unroll
            for (int b = 0; b < 4; b++) acc[a][b] = 0.f;

#pragma unroll
        for (int k = 0; k < H2; k++) {
            float w = su.p4.swd[k];
            float4 a0 = *(const float4*)&su.p4.sAt[k][ty * 4];
            float4 b0 = *(const float4*)&su.p4.sBt[k][tx * 4];
            float av[4] = {a0.x, a0.y, a0.z, a0.w};
            float bv[4] = {b0.x, b0.y, b0.z, b0.w};
#pragma unroll
            for (int a = 0; a < 4; a++)
#pragma unroll
                for (int b = 0; b < 4; b++)
                    acc[a][b] += fmaxf(av[a] + bv[b], 0.f) * w;
        }

        float bd = su.p4.sbd;
#pragma unroll
        for (int a = 0; a < 4; a++) {
            int i = i0 + ty * 4 + a;
            int basei = i * (2 * NND - 1 - i) / 2 - i - 1;  // e = basei + j
            int jlo = j0 + tx * 4;
#pragma unroll
            for (int b = 0; b < 4; b++) {
                int j = jlo + b;
                if (j > i) {
                    float d  = acc[a][b] + bd;  // z0 - z1
                    float ex = __expf(-d);
                    float p0 = __fdividef(1.f, 1.f + ex);
                    float p1 = 1.f - p0;
                    ((float2*)out)[basei + j] = make_float2(p0, p1);
                }
            }
        }
    }
}

// ---------------- launch ----------------
extern "C" void kernel_launch(void* const* d_in, const int* in_sizes, int n_in,
                              void* d_out, int out_size) {
    const float* x    = (const float*)d_in[0];
    const float* cent = (const float*)d_in[1];
    const float* Ws1  = (const float*)d_in[2];
    const float* Wn1  = (const float*)d_in[3];
    const float* b1   = (const float*)d_in[4];
    const float* Ws2  = (const float*)d_in[5];
    const float* Wn2  = (const float*)d_in[6];
    const float* b2   = (const float*)d_in[7];
    const float* Wm1  = (const float*)d_in[8];
    const float* bm1  = (const float*)d_in[9];
    const float* Wm2  = (const float*)d_in[10];
    const float* bm2  = (const float*)d_in[11];
    float* out = (float*)d_out;

    k_fused<<<GRID_N, 512>>>(x, cent, Ws1, Wn1, b1, Ws2, Wn2, b2,
                             Wm1, bm1, Wm2, bm2, out);
}